// round 3
// baseline (speedup 1.0000x reference)
#include <cuda_runtime.h>
#include <math.h>

#define BB 64
#define NN 4096
#define DD 128
#define SS 7
#define HH 128
#define MM 256
#define G3 (3*HH)
#define CH 16                 // chunks per batch in streaming pass
#define RPB (NN/CH)           // rows per block = 256
#define RPW (RPB/8)           // rows per warp = 32
#define LN_EPS 1e-5f
#define EPSF 1e-8f
#define SCALE 0.08838834764831845f   // 128^-0.5

// ---------------- device scratch (no allocations allowed) ----------------
__device__ __align__(16) float g_slots[BB*SS*HH];
__device__ __align__(16) float g_u[BB*SS*DD];     // scale*ln_in_g[d]*qk[b,s,d]
__device__ float g_e[BB*SS];                      // sum_d u
__device__ float g_c[BB*SS];                      // scale*sum_d ln_in_b*qk
__device__ __align__(16) float g_acc[BB*SS*DD];   // sum_n w*invsd*x
__device__ float g_sumWM[BB*SS];                  // sum_n w*m*invsd
__device__ float g_W[BB*SS];                      // sum_n w

static __device__ __forceinline__ float dot4(float4 a, float4 b) {
    return a.x*b.x + a.y*b.y + a.z*b.z + a.w*b.w;
}

// ---------------- slots init: mu + exp(log_sigma)*init, first 128 dims ----
__global__ void k_init(const float* __restrict__ sinit,
                       const float* __restrict__ mu,
                       const float* __restrict__ lsig)
{
    int i = blockIdx.x*blockDim.x + threadIdx.x;
    if (i >= BB*SS*HH) return;
    int h  = i & (HH-1);
    int bs = i >> 7;
    g_slots[i] = mu[h] + expf(lsig[h]) * sinit[bs*(HH+4) + h];
}

// ---------------- per-iteration prep: slot LN -> q -> qk -> u,e,c; zero accs
__global__ void __launch_bounds__(128) k_prep(
    const float* __restrict__ ln_s_g, const float* __restrict__ ln_s_b,
    const float* __restrict__ ln_in_g, const float* __restrict__ ln_in_b,
    const float* __restrict__ Wq, const float* __restrict__ Wk)
{
    __shared__ __align__(16) float sn[SS][DD];
    __shared__ __align__(16) float q[SS][DD];
    __shared__ float red_e[SS], red_c[SS];
    int b = blockIdx.x;
    int tid = threadIdx.x;
    int wid = tid >> 5, lane = tid & 31;

    if (tid < SS) { red_e[tid] = 0.f; red_c[tid] = 0.f; }

    // LayerNorm of current slots (warp per row)
    for (int s = wid; s < SS; s += 4) {
        float4 x = *(const float4*)&g_slots[(b*SS+s)*HH + lane*4];
        float sm = x.x+x.y+x.z+x.w;
        float sq = x.x*x.x + x.y*x.y + x.z*x.z + x.w*x.w;
        #pragma unroll
        for (int o = 16; o; o >>= 1) {
            sm += __shfl_xor_sync(0xffffffffu, sm, o);
            sq += __shfl_xor_sync(0xffffffffu, sq, o);
        }
        float m   = sm * (1.f/HH);
        float inv = rsqrtf(sq*(1.f/HH) - m*m + LN_EPS);
        int d = lane*4;
        sn[s][d+0] = (x.x-m)*inv*ln_s_g[d+0] + ln_s_b[d+0];
        sn[s][d+1] = (x.y-m)*inv*ln_s_g[d+1] + ln_s_b[d+1];
        sn[s][d+2] = (x.z-m)*inv*ln_s_g[d+2] + ln_s_b[d+2];
        sn[s][d+3] = (x.w-m)*inv*ln_s_g[d+3] + ln_s_b[d+3];
    }
    __syncthreads();

    // q[s][h] = sum_d sn[s][d]*Wq[h][d]   (thread = h)
    {
        int h = tid;
        float acc[SS];
        #pragma unroll
        for (int s = 0; s < SS; s++) acc[s] = 0.f;
        const float4* wr = (const float4*)(Wq + h*HH);
        for (int k = 0; k < DD/4; k++) {
            float4 w = __ldg(&wr[k]);
            #pragma unroll
            for (int s = 0; s < SS; s++)
                acc[s] += dot4(w, *(const float4*)&sn[s][k*4]);
        }
        #pragma unroll
        for (int s = 0; s < SS; s++) q[s][h] = acc[s];
    }
    __syncthreads();

    // qk[s][d] = sum_h q[s][h]*Wk[h][d]; then u, and partial e, c   (thread = d)
    {
        int d = tid;
        float acc[SS];
        #pragma unroll
        for (int s = 0; s < SS; s++) acc[s] = 0.f;
        for (int h4 = 0; h4 < DD/4; h4++) {
            float w0 = __ldg(&Wk[(h4*4+0)*HH + d]);
            float w1 = __ldg(&Wk[(h4*4+1)*HH + d]);
            float w2 = __ldg(&Wk[(h4*4+2)*HH + d]);
            float w3 = __ldg(&Wk[(h4*4+3)*HH + d]);
            #pragma unroll
            for (int s = 0; s < SS; s++) {
                float4 qv = *(const float4*)&q[s][h4*4];
                acc[s] += qv.x*w0 + qv.y*w1 + qv.z*w2 + qv.w*w3;
            }
        }
        float gg  = ln_in_g[d];
        float bbv = ln_in_b[d];
        float pe[SS], pc[SS];
        #pragma unroll
        for (int s = 0; s < SS; s++) {
            float u = SCALE * gg * acc[s];
            g_u[(b*SS+s)*DD + d] = u;
            pe[s] = u;
            pc[s] = SCALE * bbv * acc[s];
        }
        #pragma unroll
        for (int o = 16; o; o >>= 1) {
            #pragma unroll
            for (int s = 0; s < SS; s++) {
                pe[s] += __shfl_xor_sync(0xffffffffu, pe[s], o);
                pc[s] += __shfl_xor_sync(0xffffffffu, pc[s], o);
            }
        }
        if (lane == 0) {
            #pragma unroll
            for (int s = 0; s < SS; s++) {
                atomicAdd(&red_e[s], pe[s]);
                atomicAdd(&red_c[s], pc[s]);
            }
        }
    }
    // zero global accumulators for this batch
    for (int i = tid; i < SS*DD; i += 128) g_acc[b*SS*DD + i] = 0.f;
    if (tid < SS) { g_sumWM[b*SS+tid] = 0.f; g_W[b*SS+tid] = 0.f; }
    __syncthreads();
    if (tid < SS) { g_e[b*SS+tid] = red_e[tid]; g_c[b*SS+tid] = red_c[tid]; }
}

// ---------------- streaming pass over inputs: fused LN + logits + softmax + accumulate
__global__ void __launch_bounds__(256) k_pass(const float* __restrict__ inputs)
{
    __shared__ __align__(16) float red[SS][8][DD];
    __shared__ float wred[8][2*SS];
    int b = blockIdx.y, chunk = blockIdx.x;
    int tid = threadIdx.x, wid = tid >> 5, lane = tid & 31;

    float4 u4[SS]; float ee[SS], cc[SS];
    #pragma unroll
    for (int s = 0; s < SS; s++) {
        u4[s] = *(const float4*)&g_u[(b*SS+s)*DD + lane*4];
        ee[s] = g_e[b*SS+s];
        cc[s] = g_c[b*SS+s];
    }
    float4 a4[SS]; float aW[SS], aM[SS];
    #pragma unroll
    for (int s = 0; s < SS; s++) {
        a4[s] = make_float4(0.f,0.f,0.f,0.f);
        aW[s] = 0.f; aM[s] = 0.f;
    }

    const float4* in4 = (const float4*)(inputs +
        ((size_t)b*NN + (size_t)chunk*RPB + (size_t)wid*RPW) * DD);

    float4 x = __ldg(&in4[lane]);
    for (int i = 0; i < RPW; i++) {
        float4 xn = x;
        if (i + 1 < RPW) xn = __ldg(&in4[(i+1)*32 + lane]);

        float p[9];
        p[0] = x.x + x.y + x.z + x.w;
        p[1] = dot4(x, x);
        #pragma unroll
        for (int s = 0; s < SS; s++) p[2+s] = dot4(x, u4[s]);
        #pragma unroll
        for (int o = 16; o; o >>= 1) {
            #pragma unroll
            for (int j = 0; j < 9; j++)
                p[j] += __shfl_xor_sync(0xffffffffu, p[j], o);
        }
        float m   = p[0] * (1.f/DD);
        float inv = rsqrtf(p[1]*(1.f/DD) - m*m + LN_EPS);
        float lg[SS];
        float mx = -1e30f;
        #pragma unroll
        for (int s = 0; s < SS; s++) {
            lg[s] = (p[2+s] - m*ee[s])*inv + cc[s];
            mx = fmaxf(mx, lg[s]);
        }
        float w[SS], sum = 0.f;
        #pragma unroll
        for (int s = 0; s < SS; s++) { w[s] = __expf(lg[s]-mx); sum += w[s]; }
        float isum = __fdividef(1.f, sum);
        #pragma unroll
        for (int s = 0; s < SS; s++) {
            float ws = w[s]*isum + EPSF;
            float as = ws*inv;
            aW[s] += ws;
            aM[s] += as*m;
            a4[s].x += as*x.x; a4[s].y += as*x.y;
            a4[s].z += as*x.z; a4[s].w += as*x.w;
        }
        x = xn;
    }

    // cross-warp combine via smem, then one atomicAdd per element
    #pragma unroll
    for (int s = 0; s < SS; s++) *(float4*)&red[s][wid][lane*4] = a4[s];
    if (lane == 0) {
        #pragma unroll
        for (int s = 0; s < SS; s++) { wred[wid][s] = aW[s]; wred[wid][SS+s] = aM[s]; }
    }
    __syncthreads();
    if (tid < SS*32) {
        int s = tid >> 5, l = tid & 31;
        float4 t = make_float4(0.f,0.f,0.f,0.f);
        #pragma unroll
        for (int w = 0; w < 8; w++) {
            float4 r = *(const float4*)&red[s][w][l*4];
            t.x += r.x; t.y += r.y; t.z += r.z; t.w += r.w;
        }
        float* dst = &g_acc[(b*SS+s)*DD + l*4];
        atomicAdd(dst+0, t.x); atomicAdd(dst+1, t.y);
        atomicAdd(dst+2, t.z); atomicAdd(dst+3, t.w);
    }
    if (tid < 2*SS) {
        float t = 0.f;
        #pragma unroll
        for (int w = 0; w < 8; w++) t += wred[w][tid];
        if (tid < SS) atomicAdd(&g_W[b*SS+tid], t);
        else          atomicAdd(&g_sumWM[b*SS+tid-SS], t);
    }
}

// ---------------- slot update: updates -> Wv -> GRU -> MLP residual -------
__global__ void __launch_bounds__(512) k_update(
    const float* __restrict__ ln_in_g, const float* __restrict__ ln_in_b,
    const float* __restrict__ ln_m_g,  const float* __restrict__ ln_m_b,
    const float* __restrict__ Wv,   const float* __restrict__ W_ih,
    const float* __restrict__ W_hh, const float* __restrict__ b_ih,
    const float* __restrict__ b_hh, const float* __restrict__ w1,
    const float* __restrict__ b1,   const float* __restrict__ w2,
    const float* __restrict__ b2)
{
    __shared__ __align__(16) float sp [SS*HH];
    __shared__ __align__(16) float y  [SS*HH];   // updates-pre-Wv, then slots_mid
    __shared__ __align__(16) float upd[SS*HH];
    __shared__ __align__(16) float gi [SS*G3];
    __shared__ __align__(16) float gh [SS*G3];
    __shared__ __align__(16) float snm[SS*HH];
    __shared__ __align__(16) float hid[SS*MM];
    __shared__ float Ws[SS], SWM[SS];

    int b = blockIdx.x, tid = threadIdx.x;
    if (tid < SS) { Ws[tid] = g_W[b*SS+tid]; SWM[tid] = g_sumWM[b*SS+tid]; }
    for (int i = tid; i < SS*HH; i += 512) sp[i] = g_slots[b*SS*HH + i];
    __syncthreads();

    // y = (g*(acc - sumWM) + b*W) / W
    for (int i = tid; i < SS*DD; i += 512) {
        int s = i >> 7, d = i & 127;
        float wv = Ws[s];
        y[i] = (ln_in_g[d]*(g_acc[b*SS*DD+i] - SWM[s]) + ln_in_b[d]*wv)
               * __fdividef(1.f, wv);
    }
    __syncthreads();

    // upd = y @ Wv.T
    for (int o = tid; o < SS*HH; o += 512) {
        int s = o >> 7, h = o & 127;
        const float4* w  = (const float4*)(Wv + h*DD);
        const float4* xv = (const float4*)(y + s*DD);
        float a = 0.f;
        #pragma unroll 8
        for (int k = 0; k < DD/4; k++) a += dot4(__ldg(&w[k]), xv[k]);
        upd[o] = a;
    }
    __syncthreads();

    // gi = upd @ W_ih.T + b_ih ; gh = sp @ W_hh.T + b_hh  (fused)
    for (int o = tid; o < SS*G3; o += 512) {
        int s = o / G3, j = o - s*G3;
        const float4* wi = (const float4*)(W_ih + j*HH);
        const float4* wh = (const float4*)(W_hh + j*HH);
        const float4* xu = (const float4*)(upd + s*HH);
        const float4* xp = (const float4*)(sp  + s*HH);
        float ai = 0.f, ah = 0.f;
        #pragma unroll 4
        for (int k = 0; k < HH/4; k++) {
            ai += dot4(__ldg(&wi[k]), xu[k]);
            ah += dot4(__ldg(&wh[k]), xp[k]);
        }
        gi[s*G3+j] = ai + b_ih[j];
        gh[s*G3+j] = ah + b_hh[j];
    }
    __syncthreads();

    // GRU gates -> slots_mid (reuse y)
    for (int i = tid; i < SS*HH; i += 512) {
        int s = i >> 7, h = i & 127;
        float r  = 1.f/(1.f + expf(-(gi[s*G3+h]       + gh[s*G3+h])));
        float z  = 1.f/(1.f + expf(-(gi[s*G3+HH+h]    + gh[s*G3+HH+h])));
        float nn = tanhf(gi[s*G3+2*HH+h] + r*gh[s*G3+2*HH+h]);
        y[i] = (1.f - z)*nn + z*sp[i];
    }
    __syncthreads();

    // LayerNorm (ln_m) of slots_mid, warp per row
    {
        int wid = tid >> 5, lane = tid & 31;
        if (wid < SS) {
            float4 x = *(const float4*)&y[wid*HH + lane*4];
            float sm = x.x+x.y+x.z+x.w;
            float sq = dot4(x, x);
            #pragma unroll
            for (int o = 16; o; o >>= 1) {
                sm += __shfl_xor_sync(0xffffffffu, sm, o);
                sq += __shfl_xor_sync(0xffffffffu, sq, o);
            }
            float m   = sm * (1.f/HH);
            float inv = rsqrtf(sq*(1.f/HH) - m*m + LN_EPS);
            int d = lane*4;
            snm[wid*HH+d+0] = (x.x-m)*inv*ln_m_g[d+0] + ln_m_b[d+0];
            snm[wid*HH+d+1] = (x.y-m)*inv*ln_m_g[d+1] + ln_m_b[d+1];
            snm[wid*HH+d+2] = (x.z-m)*inv*ln_m_g[d+2] + ln_m_b[d+2];
            snm[wid*HH+d+3] = (x.w-m)*inv*ln_m_g[d+3] + ln_m_b[d+3];
        }
    }
    __syncthreads();

    // hid = relu(snm @ w1.T + b1)
    for (int o = tid; o < SS*MM; o += 512) {
        int s = o >> 8, j = o & 255;
        const float4* w  = (const float4*)(w1 + j*HH);
        const float4* xs = (const float4*)(snm + s*HH);
        float a = 0.f;
        #pragma unroll 8
        for (int k = 0; k < HH/4; k++) a += dot4(__ldg(&w[k]), xs[k]);
        hid[o] = fmaxf(a + b1[j], 0.f);
    }
    __syncthreads();

    // slots = slots_mid + hid @ w2.T + b2
    for (int o = tid; o < SS*HH; o += 512) {
        int s = o >> 7, d = o & 127;
        const float4* w  = (const float4*)(w2 + d*MM);
        const float4* xh = (const float4*)(hid + s*MM);
        float a = 0.f;
        #pragma unroll 8
        for (int k = 0; k < MM/4; k++) a += dot4(__ldg(&w[k]), xh[k]);
        g_slots[b*SS*HH + o] = y[o] + a + b2[d];
    }
}

// ---------------- copy result out ----------------
__global__ void k_copy(float* __restrict__ out)
{
    int i = blockIdx.x*blockDim.x + threadIdx.x;
    if (i < BB*SS*HH) out[i] = g_slots[i];
}

// ---------------- launch ----------------
extern "C" void kernel_launch(void* const* d_in, const int* in_sizes, int n_in,
                              void* d_out, int out_size)
{
    const float* inputs     = (const float*)d_in[0];
    const float* slots_init = (const float*)d_in[1];
    const float* ln_in_g    = (const float*)d_in[2];
    const float* ln_in_b    = (const float*)d_in[3];
    const float* ln_s_g     = (const float*)d_in[4];
    const float* ln_s_b     = (const float*)d_in[5];
    const float* ln_m_g     = (const float*)d_in[6];
    const float* ln_m_b     = (const float*)d_in[7];
    const float* Wq         = (const float*)d_in[8];
    const float* Wk         = (const float*)d_in[9];
    const float* Wv         = (const float*)d_in[10];
    const float* W_ih       = (const float*)d_in[11];
    const float* W_hh       = (const float*)d_in[12];
    const float* b_ih       = (const float*)d_in[13];
    const float* b_hh       = (const float*)d_in[14];
    const float* mlp_w1     = (const float*)d_in[15];
    const float* mlp_b1     = (const float*)d_in[16];
    const float* mlp_w2     = (const float*)d_in[17];
    const float* mlp_b2     = (const float*)d_in[18];
    const float* slots_mu   = (const float*)d_in[19];
    const float* slots_lsig = (const float*)d_in[20];

    k_init<<<(BB*SS*HH + 255)/256, 256>>>(slots_init, slots_mu, slots_lsig);

    for (int it = 0; it < 3; it++) {
        k_prep<<<BB, 128>>>(ln_s_g, ln_s_b, ln_in_g, ln_in_b, Wq, Wk);
        k_pass<<<dim3(CH, BB), 256>>>(inputs);
        k_update<<<BB, 512>>>(ln_in_g, ln_in_b, ln_m_g, ln_m_b,
                              Wv, W_ih, W_hh, b_ih, b_hh,
                              mlp_w1, mlp_b1, mlp_w2, mlp_b2);
    }

    k_copy<<<(BB*SS*HH + 255)/256, 256>>>((float*)d_out);
}

// round 4
// speedup vs baseline: 1.9329x; 1.9329x over previous
#include <cuda_runtime.h>
#include <math.h>

#define BB 64
#define NN 4096
#define DD 128
#define SS 7
#define HH 128
#define MM 256
#define G3 (3*HH)
#define CH 16                 // chunks per batch in streaming pass
#define RPB (NN/CH)           // rows per block = 256
#define RPW (RPB/8)           // rows per warp = 32
#define NPAIR (RPW/2)         // row-pairs per warp = 16
#define LN_EPS 1e-5f
#define EPSF 1e-8f
#define SCALE 0.08838834764831845f   // 128^-0.5

// ---------------- device scratch (no allocations allowed) ----------------
__device__ __align__(16) float g_slots[BB*SS*HH];
__device__ __align__(16) float g_u[BB*SS*DD];     // scale*ln_in_g[d]*qk[b,s,d]
__device__ float g_e[BB*SS];                      // sum_d u
__device__ float g_c[BB*SS];                      // scale*sum_d ln_in_b*qk
__device__ __align__(16) float g_acc[BB*SS*DD];   // sum_n w*invsd*x
__device__ float g_sumWM[BB*SS];                  // sum_n w*m*invsd
__device__ float g_W[BB*SS];                      // sum_n w
__device__ __align__(16) float g_upd[BB*SS*HH];   // attention updates after Wv
__device__ __align__(16) float g_gi[BB*SS*G3];
__device__ __align__(16) float g_gh[BB*SS*G3];

static __device__ __forceinline__ float dot4(float4 a, float4 b) {
    return a.x*b.x + a.y*b.y + a.z*b.z + a.w*b.w;
}

// ---------------- slots init: mu + exp(log_sigma)*init, first 128 dims ----
__global__ void k_init(const float* __restrict__ sinit,
                       const float* __restrict__ mu,
                       const float* __restrict__ lsig)
{
    int i = blockIdx.x*blockDim.x + threadIdx.x;
    if (i >= BB*SS*HH) return;
    int h  = i & (HH-1);
    int bs = i >> 7;
    g_slots[i] = mu[h] + expf(lsig[h]) * sinit[bs*(HH+4) + h];
}

// ---------------- per-iteration prep: slot LN -> q -> qk -> u,e,c; zero accs
__global__ void __launch_bounds__(128) k_prep(
    const float* __restrict__ ln_s_g, const float* __restrict__ ln_s_b,
    const float* __restrict__ ln_in_g, const float* __restrict__ ln_in_b,
    const float* __restrict__ Wq, const float* __restrict__ Wk)
{
    __shared__ __align__(16) float sn[SS][DD];
    __shared__ __align__(16) float q[SS][DD];
    __shared__ float red_e[SS], red_c[SS];
    int b = blockIdx.x;
    int tid = threadIdx.x;
    int wid = tid >> 5, lane = tid & 31;

    if (tid < SS) { red_e[tid] = 0.f; red_c[tid] = 0.f; }

    // LayerNorm of current slots (warp per row)
    for (int s = wid; s < SS; s += 4) {
        float4 x = *(const float4*)&g_slots[(b*SS+s)*HH + lane*4];
        float sm = x.x+x.y+x.z+x.w;
        float sq = dot4(x, x);
        #pragma unroll
        for (int o = 16; o; o >>= 1) {
            sm += __shfl_xor_sync(0xffffffffu, sm, o);
            sq += __shfl_xor_sync(0xffffffffu, sq, o);
        }
        float m   = sm * (1.f/HH);
        float inv = rsqrtf(sq*(1.f/HH) - m*m + LN_EPS);
        int d = lane*4;
        sn[s][d+0] = (x.x-m)*inv*ln_s_g[d+0] + ln_s_b[d+0];
        sn[s][d+1] = (x.y-m)*inv*ln_s_g[d+1] + ln_s_b[d+1];
        sn[s][d+2] = (x.z-m)*inv*ln_s_g[d+2] + ln_s_b[d+2];
        sn[s][d+3] = (x.w-m)*inv*ln_s_g[d+3] + ln_s_b[d+3];
    }
    __syncthreads();

    // q[s][h] = sum_d sn[s][d]*Wq[h][d]   (thread = h)
    {
        int h = tid;
        float acc[SS];
        #pragma unroll
        for (int s = 0; s < SS; s++) acc[s] = 0.f;
        const float4* wr = (const float4*)(Wq + h*HH);
        for (int k = 0; k < DD/4; k++) {
            float4 w = __ldg(&wr[k]);
            #pragma unroll
            for (int s = 0; s < SS; s++)
                acc[s] += dot4(w, *(const float4*)&sn[s][k*4]);
        }
        #pragma unroll
        for (int s = 0; s < SS; s++) q[s][h] = acc[s];
    }
    __syncthreads();

    // qk[s][d] = sum_h q[s][h]*Wk[h][d]; then u, and partial e, c   (thread = d)
    {
        int d = tid;
        float acc[SS];
        #pragma unroll
        for (int s = 0; s < SS; s++) acc[s] = 0.f;
        for (int h4 = 0; h4 < DD/4; h4++) {
            float w0 = __ldg(&Wk[(h4*4+0)*HH + d]);
            float w1 = __ldg(&Wk[(h4*4+1)*HH + d]);
            float w2 = __ldg(&Wk[(h4*4+2)*HH + d]);
            float w3 = __ldg(&Wk[(h4*4+3)*HH + d]);
            #pragma unroll
            for (int s = 0; s < SS; s++) {
                float4 qv = *(const float4*)&q[s][h4*4];
                acc[s] += qv.x*w0 + qv.y*w1 + qv.z*w2 + qv.w*w3;
            }
        }
        float gg  = ln_in_g[d];
        float bbv = ln_in_b[d];
        float pe[SS], pc[SS];
        #pragma unroll
        for (int s = 0; s < SS; s++) {
            float u = SCALE * gg * acc[s];
            g_u[(b*SS+s)*DD + d] = u;
            pe[s] = u;
            pc[s] = SCALE * bbv * acc[s];
        }
        #pragma unroll
        for (int o = 16; o; o >>= 1) {
            #pragma unroll
            for (int s = 0; s < SS; s++) {
                pe[s] += __shfl_xor_sync(0xffffffffu, pe[s], o);
                pc[s] += __shfl_xor_sync(0xffffffffu, pc[s], o);
            }
        }
        if (lane == 0) {
            #pragma unroll
            for (int s = 0; s < SS; s++) {
                atomicAdd(&red_e[s], pe[s]);
                atomicAdd(&red_c[s], pc[s]);
            }
        }
    }
    // zero global accumulators for this batch
    for (int i = tid; i < SS*DD; i += 128) g_acc[b*SS*DD + i] = 0.f;
    if (tid < SS) { g_sumWM[b*SS+tid] = 0.f; g_W[b*SS+tid] = 0.f; }
    __syncthreads();
    if (tid < SS) { g_e[b*SS+tid] = red_e[tid]; g_c[b*SS+tid] = red_c[tid]; }
}

// ---------------- streaming pass: 16 lanes per row, 2 rows per warp -------
__global__ void __launch_bounds__(256, 1) k_pass(const float* __restrict__ inputs)
{
    __shared__ __align__(16) float red[SS][8][DD];
    __shared__ float wred[8][2*SS];
    int b = blockIdx.y, chunk = blockIdx.x;
    int tid = threadIdx.x, wid = tid >> 5, lane = tid & 31;
    int sub = lane & 15;      // position within row (float4 granularity)
    int hf  = lane >> 4;      // which row of the pair

    // each lane caches float4 idx {sub, sub+16} of each u row
    float4 u0[SS], u1[SS]; float ee[SS], cc[SS];
    #pragma unroll
    for (int s = 0; s < SS; s++) {
        const float4* ur = (const float4*)&g_u[(b*SS+s)*DD];
        u0[s] = ur[sub];
        u1[s] = ur[sub+16];
        ee[s] = g_e[b*SS+s];
        cc[s] = g_c[b*SS+s];
    }
    float4 a0[SS], a1[SS]; float aW[SS], aM[SS];
    #pragma unroll
    for (int s = 0; s < SS; s++) {
        a0[s] = make_float4(0.f,0.f,0.f,0.f);
        a1[s] = make_float4(0.f,0.f,0.f,0.f);
        aW[s] = 0.f; aM[s] = 0.f;
    }

    const float4* in4 = (const float4*)(inputs +
        ((size_t)b*NN + (size_t)chunk*RPB + (size_t)wid*RPW) * DD);

    float4 x0 = __ldg(&in4[hf*32 + sub]);
    float4 x1 = __ldg(&in4[hf*32 + 16 + sub]);
    for (int i = 0; i < NPAIR; i++) {
        float4 n0 = x0, n1 = x1;
        if (i + 1 < NPAIR) {
            int off = (2*(i+1) + hf)*32;
            n0 = __ldg(&in4[off + sub]);
            n1 = __ldg(&in4[off + 16 + sub]);
        }

        float p[9];
        p[0] = (x0.x + x0.y + x0.z + x0.w) + (x1.x + x1.y + x1.z + x1.w);
        p[1] = dot4(x0, x0) + dot4(x1, x1);
        #pragma unroll
        for (int s = 0; s < SS; s++) p[2+s] = dot4(x0, u0[s]) + dot4(x1, u1[s]);
        #pragma unroll
        for (int o = 8; o; o >>= 1) {      // reduce within 16-lane group
            #pragma unroll
            for (int j = 0; j < 9; j++)
                p[j] += __shfl_xor_sync(0xffffffffu, p[j], o);
        }
        float m   = p[0] * (1.f/DD);
        float inv = rsqrtf(p[1]*(1.f/DD) - m*m + LN_EPS);
        float lg[SS];
        float mx = -1e30f;
        #pragma unroll
        for (int s = 0; s < SS; s++) {
            lg[s] = (p[2+s] - m*ee[s])*inv + cc[s];
            mx = fmaxf(mx, lg[s]);
        }
        float w[SS], sum = 0.f;
        #pragma unroll
        for (int s = 0; s < SS; s++) { w[s] = __expf(lg[s]-mx); sum += w[s]; }
        float isum = __fdividef(1.f, sum);
        #pragma unroll
        for (int s = 0; s < SS; s++) {
            float ws = w[s]*isum + EPSF;
            float as = ws*inv;
            aW[s] += ws;
            aM[s] += as*m;
            a0[s].x += as*x0.x; a0[s].y += as*x0.y;
            a0[s].z += as*x0.z; a0[s].w += as*x0.w;
            a1[s].x += as*x1.x; a1[s].y += as*x1.y;
            a1[s].z += as*x1.z; a1[s].w += as*x1.w;
        }
        x0 = n0; x1 = n1;
    }

    // combine the two 16-lane halves (same d-positions, different rows)
    #pragma unroll
    for (int s = 0; s < SS; s++) {
        a0[s].x += __shfl_xor_sync(0xffffffffu, a0[s].x, 16);
        a0[s].y += __shfl_xor_sync(0xffffffffu, a0[s].y, 16);
        a0[s].z += __shfl_xor_sync(0xffffffffu, a0[s].z, 16);
        a0[s].w += __shfl_xor_sync(0xffffffffu, a0[s].w, 16);
        a1[s].x += __shfl_xor_sync(0xffffffffu, a1[s].x, 16);
        a1[s].y += __shfl_xor_sync(0xffffffffu, a1[s].y, 16);
        a1[s].z += __shfl_xor_sync(0xffffffffu, a1[s].z, 16);
        a1[s].w += __shfl_xor_sync(0xffffffffu, a1[s].w, 16);
        aW[s] += __shfl_xor_sync(0xffffffffu, aW[s], 16);
        aM[s] += __shfl_xor_sync(0xffffffffu, aM[s], 16);
    }

    // write per-warp sums to smem (half0 -> float4 idx sub, half1 -> sub+16)
    #pragma unroll
    for (int s = 0; s < SS; s++) {
        if (hf == 0) *(float4*)&red[s][wid][sub*4]        = a0[s];
        else         *(float4*)&red[s][wid][(sub+16)*4]   = a1[s];
    }
    if (lane == 0) {
        #pragma unroll
        for (int s = 0; s < SS; s++) { wred[wid][s] = aW[s]; wred[wid][SS+s] = aM[s]; }
    }
    __syncthreads();
    if (tid < SS*32) {
        int s = tid >> 5, l = tid & 31;
        float4 t = make_float4(0.f,0.f,0.f,0.f);
        #pragma unroll
        for (int w = 0; w < 8; w++) {
            float4 r = *(const float4*)&red[s][w][l*4];
            t.x += r.x; t.y += r.y; t.z += r.z; t.w += r.w;
        }
        float* dst = &g_acc[(b*SS+s)*DD + l*4];
        atomicAdd(dst+0, t.x); atomicAdd(dst+1, t.y);
        atomicAdd(dst+2, t.z); atomicAdd(dst+3, t.w);
    }
    if (tid < 2*SS) {
        float t = 0.f;
        #pragma unroll
        for (int w = 0; w < 8; w++) t += wred[w][tid];
        if (tid < SS) atomicAdd(&g_W[b*SS+tid], t);
        else          atomicAdd(&g_sumWM[b*SS+tid-SS], t);
    }
}

// ---------------- update A: finish attention updates, apply Wv ------------
__global__ void __launch_bounds__(128) k_updA(
    const float* __restrict__ ln_in_g, const float* __restrict__ ln_in_b,
    const float* __restrict__ Wv)
{
    __shared__ __align__(16) float y[SS*DD];
    __shared__ float Ws[SS], SWM[SS];
    int b = blockIdx.x, tid = threadIdx.x;
    if (tid < SS) { Ws[tid] = g_W[b*SS+tid]; SWM[tid] = g_sumWM[b*SS+tid]; }
    __syncthreads();

    for (int i = tid; i < SS*DD; i += 128) {
        int s = i >> 7, d = i & 127;
        float wv = Ws[s];
        y[i] = (ln_in_g[d]*(g_acc[b*SS*DD+i] - SWM[s]) + ln_in_b[d]*wv)
               * __fdividef(1.f, wv);
    }
    __syncthreads();

    // upd[s][h] = y[s] . Wv[h]   (thread = h, 7-slot weight reuse)
    int h = tid;
    float acc[SS];
    #pragma unroll
    for (int s = 0; s < SS; s++) acc[s] = 0.f;
    const float4* w = (const float4*)(Wv + h*DD);
    for (int k = 0; k < DD/4; k++) {
        float4 wv4 = __ldg(&w[k]);
        #pragma unroll
        for (int s = 0; s < SS; s++)
            acc[s] += dot4(wv4, *(const float4*)&y[s*DD + k*4]);
    }
    #pragma unroll
    for (int s = 0; s < SS; s++) g_upd[(b*SS+s)*HH + h] = acc[s];
}

// ---------------- update B: gi / gh GEMVs, tiled over (j-tile, matrix) ----
__global__ void __launch_bounds__(128) k_updB(
    const float* __restrict__ W_ih, const float* __restrict__ W_hh,
    const float* __restrict__ b_ih, const float* __restrict__ b_hh)
{
    __shared__ __align__(16) float xm[SS*HH];
    int b = blockIdx.x, tid = threadIdx.x;
    int z = blockIdx.y;
    int jt = z >> 1;
    int ishh = z & 1;

    const float* src = ishh ? (g_slots + b*SS*HH) : (g_upd + b*SS*HH);
    for (int i = tid; i < SS*HH; i += 128) xm[i] = src[i];
    __syncthreads();

    int j = jt*128 + tid;
    const float4* w = (const float4*)((ishh ? W_hh : W_ih) + j*HH);
    float acc[SS];
    #pragma unroll
    for (int s = 0; s < SS; s++) acc[s] = 0.f;
    for (int k = 0; k < HH/4; k++) {
        float4 wv = __ldg(&w[k]);
        #pragma unroll
        for (int s = 0; s < SS; s++)
            acc[s] += dot4(wv, *(const float4*)&xm[s*HH + k*4]);
    }
    float bias = (ishh ? b_hh : b_ih)[j];
    float* dst = ishh ? g_gh : g_gi;
    #pragma unroll
    for (int s = 0; s < SS; s++) dst[(b*SS+s)*G3 + j] = acc[s] + bias;
}

// ---------------- update C: GRU + LN + MLP + residual --------------------
__global__ void __launch_bounds__(256) k_updC(
    const float* __restrict__ ln_m_g, const float* __restrict__ ln_m_b,
    const float* __restrict__ w1, const float* __restrict__ b1,
    const float* __restrict__ w2, const float* __restrict__ b2,
    float* __restrict__ out)
{
    __shared__ __align__(16) float smid[SS*HH];
    __shared__ __align__(16) float snm [SS*HH];
    __shared__ __align__(16) float hid [SS*MM];
    int b = blockIdx.x, tid = threadIdx.x;
    int wid = tid >> 5, lane = tid & 31;

    // GRU gates -> slots_mid
    for (int i = tid; i < SS*HH; i += 256) {
        int s = i >> 7, h = i & 127;
        const float* gi = g_gi + (b*SS+s)*G3;
        const float* gh = g_gh + (b*SS+s)*G3;
        float r  = 1.f/(1.f + __expf(-(gi[h]        + gh[h])));
        float zz = 1.f/(1.f + __expf(-(gi[HH+h]     + gh[HH+h])));
        float nn = tanhf(gi[2*HH+h] + r*gh[2*HH+h]);
        smid[i] = (1.f - zz)*nn + zz*g_slots[b*SS*HH + i];
    }
    __syncthreads();

    // LayerNorm (ln_m), warp per slot
    if (wid < SS) {
        float4 x = *(const float4*)&smid[wid*HH + lane*4];
        float sm = x.x+x.y+x.z+x.w;
        float sq = dot4(x, x);
        #pragma unroll
        for (int o = 16; o; o >>= 1) {
            sm += __shfl_xor_sync(0xffffffffu, sm, o);
            sq += __shfl_xor_sync(0xffffffffu, sq, o);
        }
        float m   = sm * (1.f/HH);
        float inv = rsqrtf(sq*(1.f/HH) - m*m + LN_EPS);
        int d = lane*4;
        snm[wid*HH+d+0] = (x.x-m)*inv*ln_m_g[d+0] + ln_m_b[d+0];
        snm[wid*HH+d+1] = (x.y-m)*inv*ln_m_g[d+1] + ln_m_b[d+1];
        snm[wid*HH+d+2] = (x.z-m)*inv*ln_m_g[d+2] + ln_m_b[d+2];
        snm[wid*HH+d+3] = (x.w-m)*inv*ln_m_g[d+3] + ln_m_b[d+3];
    }
    __syncthreads();

    // hid = relu(snm @ w1.T + b1)   (thread = j, 7-slot reuse)
    {
        int j = tid;
        const float4* w = (const float4*)(w1 + j*HH);
        float a[SS];
        #pragma unroll
        for (int s = 0; s < SS; s++) a[s] = 0.f;
        for (int k = 0; k < HH/4; k++) {
            float4 wv = __ldg(&w[k]);
            #pragma unroll
            for (int s = 0; s < SS; s++)
                a[s] += dot4(wv, *(const float4*)&snm[s*HH + k*4]);
        }
        float bb = b1[j];
        #pragma unroll
        for (int s = 0; s < SS; s++) hid[s*MM + j] = fmaxf(a[s] + bb, 0.f);
    }
    __syncthreads();

    // slots = slots_mid + hid @ w2.T + b2   (threads 0..127, thread = d)
    if (tid < 128) {
        int d = tid;
        const float4* w = (const float4*)(w2 + d*MM);
        float a[SS];
        #pragma unroll
        for (int s = 0; s < SS; s++) a[s] = 0.f;
        for (int k = 0; k < MM/4; k++) {
            float4 wv = __ldg(&w[k]);
            #pragma unroll
            for (int s = 0; s < SS; s++)
                a[s] += dot4(wv, *(const float4*)&hid[s*MM + k*4]);
        }
        float bb = b2[d];
        #pragma unroll
        for (int s = 0; s < SS; s++) {
            float v = smid[s*HH + d] + a[s] + bb;
            g_slots[b*SS*HH + s*HH + d] = v;
            out    [b*SS*HH + s*HH + d] = v;   // last iteration's write is final
        }
    }
}

// ---------------- launch ----------------
extern "C" void kernel_launch(void* const* d_in, const int* in_sizes, int n_in,
                              void* d_out, int out_size)
{
    const float* inputs     = (const float*)d_in[0];
    const float* slots_init = (const float*)d_in[1];
    const float* ln_in_g    = (const float*)d_in[2];
    const float* ln_in_b    = (const float*)d_in[3];
    const float* ln_s_g     = (const float*)d_in[4];
    const float* ln_s_b     = (const float*)d_in[5];
    const float* ln_m_g     = (const float*)d_in[6];
    const float* ln_m_b     = (const float*)d_in[7];
    const float* Wq         = (const float*)d_in[8];
    const float* Wk         = (const float*)d_in[9];
    const float* Wv         = (const float*)d_in[10];
    const float* W_ih       = (const float*)d_in[11];
    const float* W_hh       = (const float*)d_in[12];
    const float* b_ih       = (const float*)d_in[13];
    const float* b_hh       = (const float*)d_in[14];
    const float* mlp_w1     = (const float*)d_in[15];
    const float* mlp_b1     = (const float*)d_in[16];
    const float* mlp_w2     = (const float*)d_in[17];
    const float* mlp_b2     = (const float*)d_in[18];
    const float* slots_mu   = (const float*)d_in[19];
    const float* slots_lsig = (const float*)d_in[20];

    k_init<<<(BB*SS*HH + 255)/256, 256>>>(slots_init, slots_mu, slots_lsig);

    for (int it = 0; it < 3; it++) {
        k_prep<<<BB, 128>>>(ln_s_g, ln_s_b, ln_in_g, ln_in_b, Wq, Wk);
        k_pass<<<dim3(CH, BB), 256>>>(inputs);
        k_updA<<<BB, 128>>>(ln_in_g, ln_in_b, Wv);
        k_updB<<<dim3(BB, 6), 128>>>(W_ih, W_hh, b_ih, b_hh);
        k_updC<<<BB, 256>>>(ln_m_g, ln_m_b, mlp_w1, mlp_b1, mlp_w2, mlp_b2,
                            (float*)d_out);
    }
}

// round 6
// speedup vs baseline: 2.0100x; 1.0399x over previous
#include <cuda_runtime.h>
#include <math.h>

typedef unsigned long long ull;

#define BB 64
#define NN 4096
#define DD 128
#define SS 7
#define HH 128
#define MM 256
#define TROWS 128             // rows per pass-tile
#define LN_EPS 1e-5f
#define EPSF 1e-8f
#define SCALE 0.08838834764831845f   // 128^-0.5

// ---------------- device scratch ----------------
__device__ __align__(16) float g_slots[BB*SS*HH];
__device__ __align__(16) float g_u[BB*SS*DD];     // folded: SCALE*g*qk - e/128
__device__ float g_c[BB*SS];
__device__ __align__(16) float g_acc[BB*SS*DD];   // sum_n as*x
__device__ float g_sumWM[BB*SS];                  // sum_n as*m
__device__ float g_W[BB*SS];                      // sum_n ws

// ---------------- f32x2 packed helpers ----------------
static __device__ __forceinline__ ull pk2(float lo, float hi) {
    ull r; asm("mov.b64 %0,{%1,%2};" : "=l"(r) : "f"(lo), "f"(hi)); return r;
}
static __device__ __forceinline__ void upk2(float& lo, float& hi, ull v) {
    asm("mov.b64 {%0,%1},%2;" : "=f"(lo), "=f"(hi) : "l"(v));
}
static __device__ __forceinline__ ull ffma2(ull a, ull b, ull c) {
    ull d; asm("fma.rn.f32x2 %0,%1,%2,%3;" : "=l"(d) : "l"(a), "l"(b), "l"(c)); return d;
}
static __device__ __forceinline__ ull fadd2(ull a, ull b) {
    ull d; asm("add.rn.f32x2 %0,%1,%2;" : "=l"(d) : "l"(a), "l"(b)); return d;
}
static __device__ __forceinline__ float dot4(float4 a, float4 b) {
    return a.x*b.x + a.y*b.y + a.z*b.z + a.w*b.w;
}
static __device__ __forceinline__ float hsum2(ull v) {
    float lo, hi; upk2(lo, hi, v); return lo + hi;
}

// ---------------- prep (device): slot LN -> q -> qk -> u~,c; zero accs ----
// Called by all threads of the block; work guarded to tid<128.
static __device__ void prep_dev(
    int b, int tid,
    const float* slots_sm,        // [SS*HH] current slots in smem
    float* sn, float* q, float* red,   // scratch: 896, 896, 16
    const float* __restrict__ ln_s_g, const float* __restrict__ ln_s_b,
    const float* __restrict__ ln_in_g, const float* __restrict__ ln_in_b,
    const float* __restrict__ Wq, const float* __restrict__ Wk)
{
    int wid = tid >> 5, lane = tid & 31;
    if (tid < 16) red[tid] = 0.f;
    __syncthreads();

    // LayerNorm of slots (warps 0-3, warp per slot)
    if (tid < 128) {
        for (int s = wid; s < SS; s += 4) {
            float4 x = *(const float4*)&slots_sm[s*HH + lane*4];
            float sm = x.x+x.y+x.z+x.w;
            float sq = dot4(x, x);
            #pragma unroll
            for (int o = 16; o; o >>= 1) {
                sm += __shfl_xor_sync(0xffffffffu, sm, o);
                sq += __shfl_xor_sync(0xffffffffu, sq, o);
            }
            float m   = sm * (1.f/HH);
            float inv = rsqrtf(sq*(1.f/HH) - m*m + LN_EPS);
            int d = lane*4;
            sn[s*HH+d+0] = (x.x-m)*inv*ln_s_g[d+0] + ln_s_b[d+0];
            sn[s*HH+d+1] = (x.y-m)*inv*ln_s_g[d+1] + ln_s_b[d+1];
            sn[s*HH+d+2] = (x.z-m)*inv*ln_s_g[d+2] + ln_s_b[d+2];
            sn[s*HH+d+3] = (x.w-m)*inv*ln_s_g[d+3] + ln_s_b[d+3];
        }
    }
    __syncthreads();

    // q[s][h] = sn[s] . Wq[h]
    if (tid < 128) {
        int h = tid;
        float a[SS];
        #pragma unroll
        for (int s = 0; s < SS; s++) a[s] = 0.f;
        const float4* wr = (const float4*)(Wq + h*HH);
        for (int k = 0; k < HH/4; k++) {
            float4 w = __ldg(&wr[k]);
            #pragma unroll
            for (int s = 0; s < SS; s++)
                a[s] += dot4(w, *(const float4*)&sn[s*HH + k*4]);
        }
        #pragma unroll
        for (int s = 0; s < SS; s++) q[s*HH+h] = a[s];
    }
    __syncthreads();

    float acc[SS];
    if (tid < 128) {
        int d = tid;
        #pragma unroll
        for (int s = 0; s < SS; s++) acc[s] = 0.f;
        for (int h4 = 0; h4 < HH/4; h4++) {
            float w0 = __ldg(&Wk[(h4*4+0)*HH + d]);
            float w1 = __ldg(&Wk[(h4*4+1)*HH + d]);
            float w2 = __ldg(&Wk[(h4*4+2)*HH + d]);
            float w3 = __ldg(&Wk[(h4*4+3)*HH + d]);
            #pragma unroll
            for (int s = 0; s < SS; s++) {
                float4 qv = *(const float4*)&q[s*HH + h4*4];
                acc[s] += qv.x*w0 + qv.y*w1 + qv.z*w2 + qv.w*w3;
            }
        }
        float gg  = ln_in_g[d];
        float bbv = ln_in_b[d];
        float pe[SS], pc[SS];
        #pragma unroll
        for (int s = 0; s < SS; s++) {
            pe[s] = SCALE * gg  * acc[s];
            pc[s] = SCALE * bbv * acc[s];
        }
        #pragma unroll
        for (int o = 16; o; o >>= 1) {
            #pragma unroll
            for (int s = 0; s < SS; s++) {
                pe[s] += __shfl_xor_sync(0xffffffffu, pe[s], o);
                pc[s] += __shfl_xor_sync(0xffffffffu, pc[s], o);
            }
        }
        if (lane == 0) {
            #pragma unroll
            for (int s = 0; s < SS; s++) {
                atomicAdd(&red[s],   pe[s]);
                atomicAdd(&red[8+s], pc[s]);
            }
        }
    }
    __syncthreads();

    if (tid < 128) {
        int d = tid;
        float gg = ln_in_g[d];
        #pragma unroll
        for (int s = 0; s < SS; s++)
            g_u[(b*SS+s)*DD + d] = SCALE*gg*acc[s] - red[s]*(1.f/DD);
    }
    if (tid < SS) {
        g_c[b*SS+tid]     = red[8+tid];
        g_W[b*SS+tid]     = 0.f;
        g_sumWM[b*SS+tid] = 0.f;
    }
    for (int i = tid; i < SS*DD; i += blockDim.x) g_acc[b*SS*DD + i] = 0.f;
}

// ---------------- init + first prep ----------------
__global__ void __launch_bounds__(128) k_init0(
    const float* __restrict__ sinit,
    const float* __restrict__ mu,
    const float* __restrict__ lsig,
    const float* __restrict__ ln_s_g, const float* __restrict__ ln_s_b,
    const float* __restrict__ ln_in_g, const float* __restrict__ ln_in_b,
    const float* __restrict__ Wq, const float* __restrict__ Wk)
{
    __shared__ __align__(16) float T[896*3];
    __shared__ float red[16];
    int b = blockIdx.x, tid = threadIdx.x;
    for (int i = tid; i < SS*HH; i += 128) {
        int s = i >> 7, h = i & 127;
        float v = mu[h] + expf(lsig[h]) * sinit[(b*SS+s)*(HH+4) + h];
        T[i] = v;
        g_slots[b*SS*HH + i] = v;
    }
    __syncthreads();
    prep_dev(b, tid, T, T+896, T+1792, red,
             ln_s_g, ln_s_b, ln_in_g, ln_in_b, Wq, Wk);
}

// ---------------- streaming pass: smem tile, two-pass, no shuffles --------
__global__ void __launch_bounds__(256) k_pass(const float* __restrict__ inputs)
{
    extern __shared__ float smd[];
    float* tile = smd;                        // TROWS * 132
    float* ubuf = smd + TROWS*132;            // 7*128
    ull*   wbuf = (ull*)(smd + TROWS*132 + 896);   // TROWS*9 ull
    float* sAW  = smd + TROWS*132 + 896 + TROWS*9*2;  // 7
    float* sAM  = sAW + 7;                    // 7

    int b = blockIdx.y, chunk = blockIdx.x;
    int tid = threadIdx.x, wid = tid >> 5, lane = tid & 31;

    // stage u~ and zero small reductions
    if (tid < 224)
        ((float4*)ubuf)[tid] = ((const float4*)(g_u + b*SS*DD))[tid];
    if (tid < 14) { if (tid < 7) sAW[tid] = 0.f; else sAM[tid-7] = 0.f; }

    // stage tile (TROWS x 128 floats), coalesced, pad-132 layout
    const float4* gin = (const float4*)(inputs + ((size_t)b*NN + (size_t)chunk*TROWS)*DD);
    #pragma unroll
    for (int j = 0; j < TROWS*32/256; j++) {
        int i = tid + j*256;
        int r = i >> 5, c = i & 31;
        *(float4*)&tile[r*132 + c*4] = __ldg(&gin[i]);
    }
    __syncthreads();

    // pass 1: thread = row (threads 0..127)
    if (tid < TROWS) {
        const float* xr = tile + tid*132;
        ull d2[SS], sm2 = 0ull, sq2 = 0ull;
        #pragma unroll
        for (int s = 0; s < SS; s++) d2[s] = 0ull;
        for (int k = 0; k < 32; k++) {
            ulonglong2 x = *(const ulonglong2*)(xr + k*4);
            sm2 = fadd2(sm2, x.x);
            sm2 = fadd2(sm2, x.y);
            sq2 = ffma2(x.x, x.x, sq2);
            sq2 = ffma2(x.y, x.y, sq2);
            #pragma unroll
            for (int s = 0; s < SS; s++) {
                ulonglong2 u = *(const ulonglong2*)&ubuf[s*128 + k*4];
                d2[s] = ffma2(x.x, u.x, d2[s]);
                d2[s] = ffma2(x.y, u.y, d2[s]);
            }
        }
        float m   = hsum2(sm2) * (1.f/DD);
        float inv = rsqrtf(hsum2(sq2)*(1.f/DD) - m*m + LN_EPS);
        float lg[SS], mx = -1e30f;
        #pragma unroll
        for (int s = 0; s < SS; s++) {
            lg[s] = hsum2(d2[s])*inv + __ldg(&g_c[b*SS+s]);
            mx = fmaxf(mx, lg[s]);
        }
        float w[SS], sum = 0.f;
        #pragma unroll
        for (int s = 0; s < SS; s++) { w[s] = __expf(lg[s]-mx); sum += w[s]; }
        float isum = __fdividef(1.f, sum);
        float pw[SS], pm[SS];
        #pragma unroll
        for (int s = 0; s < SS; s++) {
            float ws = w[s]*isum + EPSF;
            float as = ws*inv;
            wbuf[tid*9 + s] = pk2(as, as);
            pw[s] = ws;
            pm[s] = as*m;
        }
        #pragma unroll
        for (int o = 16; o; o >>= 1) {
            #pragma unroll
            for (int s = 0; s < SS; s++) {
                pw[s] += __shfl_xor_sync(0xffffffffu, pw[s], o);
                pm[s] += __shfl_xor_sync(0xffffffffu, pm[s], o);
            }
        }
        if (lane == 0) {
            #pragma unroll
            for (int s = 0; s < SS; s++) {
                atomicAdd(&sAW[s], pw[s]);
                atomicAdd(&sAM[s], pm[s]);
            }
        }
    }
    __syncthreads();

    // pass 2: warp per 16 rows, lanes = d
    ull acc[SS][2];
    #pragma unroll
    for (int s = 0; s < SS; s++) { acc[s][0] = 0ull; acc[s][1] = 0ull; }
    {
        int r0 = wid * (TROWS/8);
        #pragma unroll 4
        for (int i = 0; i < TROWS/8; i++) {
            int r = r0 + i;
            ulonglong2 x = *(const ulonglong2*)&tile[r*132 + lane*4];
            #pragma unroll
            for (int s = 0; s < SS; s++) {
                ull a = wbuf[r*9 + s];
                acc[s][0] = ffma2(x.x, a, acc[s][0]);
                acc[s][1] = ffma2(x.y, a, acc[s][1]);
            }
        }
    }
    __syncthreads();            // tile no longer needed
    float* red = tile;          // [7][8][128]
    #pragma unroll
    for (int s = 0; s < SS; s++) {
        float4 v;
        upk2(v.x, v.y, acc[s][0]);
        upk2(v.z, v.w, acc[s][1]);
        *(float4*)&red[(s*8+wid)*128 + lane*4] = v;
    }
    __syncthreads();
    if (tid < SS*32) {
        int s = tid >> 5, l = tid & 31;
        float4 t = make_float4(0.f,0.f,0.f,0.f);
        #pragma unroll
        for (int w = 0; w < 8; w++) {
            float4 r = *(const float4*)&red[(s*8+w)*128 + l*4];
            t.x += r.x; t.y += r.y; t.z += r.z; t.w += r.w;
        }
        float* dst = &g_acc[(b*SS+s)*DD + l*4];
        atomicAdd(dst+0, t.x); atomicAdd(dst+1, t.y);
        atomicAdd(dst+2, t.z); atomicAdd(dst+3, t.w);
    }
    if (tid < 2*SS) {
        if (tid < SS) atomicAdd(&g_W[b*SS+tid],        sAW[tid]);
        else          atomicAdd(&g_sumWM[b*SS+tid-SS], sAM[tid-SS]);
    }
}

// ---------------- fused update: y->Wv, GRU gates, GRU, LN, MLP, prep -----
#define SP   0
#define YB   896
#define UPD  896
#define PU   1792
#define GI   1792
#define GH   4480
#define SMID 7168
#define SNM  0
#define HID  896
#define PM   2688

__global__ void __launch_bounds__(256) k_upd(
    const float* __restrict__ ln_in_g, const float* __restrict__ ln_in_b,
    const float* __restrict__ ln_m_g,  const float* __restrict__ ln_m_b,
    const float* __restrict__ ln_s_g,  const float* __restrict__ ln_s_b,
    const float* __restrict__ Wq,   const float* __restrict__ Wk,
    const float* __restrict__ Wv,   const float* __restrict__ W_ih,
    const float* __restrict__ W_hh, const float* __restrict__ b_ih,
    const float* __restrict__ b_hh, const float* __restrict__ w1,
    const float* __restrict__ b1,   const float* __restrict__ w2,
    const float* __restrict__ b2,   float* __restrict__ out)
{
    __shared__ __align__(16) float S[8192];
    __shared__ float Ws[SS], SWM[SS], red[16];
    int b = blockIdx.x, tid = threadIdx.x;

    // phase 1: load prev slots + compute y
    if (tid < SS) { Ws[tid] = g_W[b*SS+tid]; SWM[tid] = g_sumWM[b*SS+tid]; }
    for (int i = tid; i < SS*HH; i += 256) S[SP+i] = g_slots[b*SS*HH + i];
    __syncthreads();
    for (int i = tid; i < SS*DD; i += 256) {
        int s = i >> 7, d = i & 127;
        float wv = Ws[s];
        S[YB+i] = (ln_in_g[d]*(g_acc[b*SS*DD+i] - SWM[s]) + ln_in_b[d]*wv)
                  * __fdividef(1.f, wv);
    }
    __syncthreads();

    // phase 2: gh = slots_prev @ W_hh.T + b_hh  (rows 0..383)
    for (int r = tid; r < 3*HH; r += 256) {
        const float* wr = W_hh + r*HH;
        ull a[SS];
        #pragma unroll
        for (int s = 0; s < SS; s++) a[s] = 0ull;
        for (int k = 0; k < 32; k++) {
            ulonglong2 wv = *(const ulonglong2*)&wr[k*4];
            #pragma unroll
            for (int s = 0; s < SS; s++) {
                ulonglong2 xv = *(const ulonglong2*)&S[SP + s*HH + k*4];
                a[s] = ffma2(wv.x, xv.x, a[s]);
                a[s] = ffma2(wv.y, xv.y, a[s]);
            }
        }
        float bias = b_hh[r];
        #pragma unroll
        for (int s = 0; s < SS; s++) S[GH + s*384 + r] = hsum2(a[s]) + bias;
    }

    // phase 3: upd partial = y @ Wv.T   (2-way k split)
    {
        int part = tid >> 7, h = tid & 127;
        const float* wr = Wv + h*DD;
        ull a[SS];
        #pragma unroll
        for (int s = 0; s < SS; s++) a[s] = 0ull;
        for (int k = part*16; k < part*16+16; k++) {
            ulonglong2 wv = *(const ulonglong2*)&wr[k*4];
            #pragma unroll
            for (int s = 0; s < SS; s++) {
                ulonglong2 xv = *(const ulonglong2*)&S[YB + s*DD + k*4];
                a[s] = ffma2(wv.x, xv.x, a[s]);
                a[s] = ffma2(wv.y, xv.y, a[s]);
            }
        }
        __syncthreads();   // all reads of y done
        #pragma unroll
        for (int s = 0; s < SS; s++) S[PU + part*896 + s*128 + h] = hsum2(a[s]);
    }
    __syncthreads();
    for (int i = tid; i < 896; i += 256) {
        float v = S[PU+i] + S[PU+896+i];
        __syncwarp();
        S[UPD+i] = v;      // overwrites y region (dead); disjoint from PU reads? no:
    }                      // PU starts at 1792, UPD at 896..1792 — disjoint, safe
    __syncthreads();

    // phase 4: gi = upd @ W_ih.T + b_ih
    for (int r = tid; r < 3*HH; r += 256) {
        const float* wr = W_ih + r*HH;
        ull a[SS];
        #pragma unroll
        for (int s = 0; s < SS; s++) a[s] = 0ull;
        for (int k = 0; k < 32; k++) {
            ulonglong2 wv = *(const ulonglong2*)&wr[k*4];
            #pragma unroll
            for (int s = 0; s < SS; s++) {
                ulonglong2 xv = *(const ulonglong2*)&S[UPD + s*HH + k*4];
                a[s] = ffma2(wv.x, xv.x, a[s]);
                a[s] = ffma2(wv.y, xv.y, a[s]);
            }
        }
        float bias = b_ih[r];
        #pragma unroll
        for (int s = 0; s < SS; s++) S[GI + s*384 + r] = hsum2(a[s]) + bias;
    }
    __syncthreads();

    // phase 5: GRU -> slots_mid
    for (int i = tid; i < SS*HH; i += 256) {
        int s = i >> 7, h = i & 127;
        float gr = S[GI + s*384 + h]       + S[GH + s*384 + h];
        float gz = S[GI + s*384 + 128 + h] + S[GH + s*384 + 128 + h];
        float r  = 1.f/(1.f + __expf(-gr));
        float z  = 1.f/(1.f + __expf(-gz));
        float nn = tanhf(S[GI + s*384 + 256 + h] + r*S[GH + s*384 + 256 + h]);
        S[SMID+i] = (1.f - z)*nn + z*S[SP+i];
    }
    __syncthreads();

    // phase 6: LayerNorm(ln_m) -> snm
    {
        int wid = tid >> 5, lane = tid & 31;
        if (wid < SS) {
            float4 x = *(const float4*)&S[SMID + wid*HH + lane*4];
            float sm = x.x+x.y+x.z+x.w;
            float sq = dot4(x, x);
            #pragma unroll
            for (int o = 16; o; o >>= 1) {
                sm += __shfl_xor_sync(0xffffffffu, sm, o);
                sq += __shfl_xor_sync(0xffffffffu, sq, o);
            }
            float m   = sm * (1.f/HH);
            float inv = rsqrtf(sq*(1.f/HH) - m*m + LN_EPS);
            int d = lane*4;
            S[SNM + wid*HH+d+0] = (x.x-m)*inv*ln_m_g[d+0] + ln_m_b[d+0];
            S[SNM + wid*HH+d+1] = (x.y-m)*inv*ln_m_g[d+1] + ln_m_b[d+1];
            S[SNM + wid*HH+d+2] = (x.z-m)*inv*ln_m_g[d+2] + ln_m_b[d+2];
            S[SNM + wid*HH+d+3] = (x.w-m)*inv*ln_m_g[d+3] + ln_m_b[d+3];
        }
    }
    __syncthreads();

    // phase 7: hid = relu(snm @ w1.T + b1)
    {
        int j = tid;
        const float* wr = w1 + j*HH;
        ull a[SS];
        #pragma unroll
        for (int s = 0; s < SS; s++) a[s] = 0ull;
        for (int k = 0; k < 32; k++) {
            ulonglong2 wv = *(const ulonglong2*)&wr[k*4];
            #pragma unroll
            for (int s = 0; s < SS; s++) {
                ulonglong2 xv = *(const ulonglong2*)&S[SNM + s*HH + k*4];
                a[s] = ffma2(wv.x, xv.x, a[s]);
                a[s] = ffma2(wv.y, xv.y, a[s]);
            }
        }
        float bb = b1[j];
        __syncthreads();   // snm reads done before HID overwrite hazard? HID=896 disjoint from SNM=0..896 — safe anyway
        #pragma unroll
        for (int s = 0; s < SS; s++) S[HID + s*MM + j] = fmaxf(hsum2(a[s]) + bb, 0.f);
    }
    __syncthreads();

    // phase 8: mlp2 partial (2-way k split over MM)
    {
        int part = tid >> 7, d = tid & 127;
        const float* wr = w2 + d*MM;
        ull a[SS];
        #pragma unroll
        for (int s = 0; s < SS; s++) a[s] = 0ull;
        for (int k = part*32; k < part*32+32; k++) {
            ulonglong2 wv = *(const ulonglong2*)&wr[k*4];
            #pragma unroll
            for (int s = 0; s < SS; s++) {
                ulonglong2 xv = *(const ulonglong2*)&S[HID + s*MM + k*4];
                a[s] = ffma2(wv.x, xv.x, a[s]);
                a[s] = ffma2(wv.y, xv.y, a[s]);
            }
        }
        #pragma unroll
        for (int s = 0; s < SS; s++) S[PM + part*896 + s*128 + d] = hsum2(a[s]);
    }
    __syncthreads();

    // phase 9: residual -> final slots (into SMID), write out + g_slots
    for (int i = tid; i < SS*HH; i += 256) {
        int d = i & 127;
        float v = S[SMID+i] + S[PM+i] + S[PM+896+i] + b2[d];
        S[SMID+i] = v;
        g_slots[b*SS*HH + i] = v;
        out[b*SS*HH + i] = v;
    }
    __syncthreads();

    // phase 10: prep for next iteration (sn=S+0, q=S+896 are dead regions)
    prep_dev(b, tid, &S[SMID], &S[0], &S[896], red,
             ln_s_g, ln_s_b, ln_in_g, ln_in_b, Wq, Wk);
}

// ---------------- launch ----------------
extern "C" void kernel_launch(void* const* d_in, const int* in_sizes, int n_in,
                              void* d_out, int out_size)
{
    const float* inputs     = (const float*)d_in[0];
    const float* slots_init = (const float*)d_in[1];
    const float* ln_in_g    = (const float*)d_in[2];
    const float* ln_in_b    = (const float*)d_in[3];
    const float* ln_s_g     = (const float*)d_in[4];
    const float* ln_s_b     = (const float*)d_in[5];
    const float* ln_m_g     = (const float*)d_in[6];
    const float* ln_m_b     = (const float*)d_in[7];
    const float* Wq         = (const float*)d_in[8];
    const float* Wk         = (const float*)d_in[9];
    const float* Wv         = (const float*)d_in[10];
    const float* W_ih       = (const float*)d_in[11];
    const float* W_hh       = (const float*)d_in[12];
    const float* b_ih       = (const float*)d_in[13];
    const float* b_hh       = (const float*)d_in[14];
    const float* mlp_w1     = (const float*)d_in[15];
    const float* mlp_b1     = (const float*)d_in[16];
    const float* mlp_w2     = (const float*)d_in[17];
    const float* mlp_b2     = (const float*)d_in[18];
    const float* slots_mu   = (const float*)d_in[19];
    const float* slots_lsig = (const float*)d_in[20];

    // dynamic smem for k_pass: tile + ubuf + wbuf + 14 floats
    const int pass_smem = (TROWS*132 + 896 + TROWS*9*2 + 16) * 4;
    cudaFuncSetAttribute(k_pass, cudaFuncAttributeMaxDynamicSharedMemorySize,
                         pass_smem);

    k_init0<<<BB, 128>>>(slots_init, slots_mu, slots_lsig,
                         ln_s_g, ln_s_b, ln_in_g, ln_in_b, Wq, Wk);

    for (int it = 0; it < 3; it++) {
        k_pass<<<dim3(NN/TROWS, BB), 256, pass_smem>>>(inputs);
        k_upd<<<BB, 256>>>(ln_in_g, ln_in_b, ln_m_g, ln_m_b,
                           ln_s_g, ln_s_b, Wq, Wk,
                           Wv, W_ih, W_hh, b_ih, b_hh,
                           mlp_w1, mlp_b1, mlp_w2, mlp_b2,
                           (float*)d_out);
    }
}